// round 1
// baseline (speedup 1.0000x reference)
#include <cuda_runtime.h>
#include <math_constants.h>

// Problem constants (fixed shapes: latents [16,2048,512], embedding [8192,512])
constexpr int DDIM  = 512;
constexpr int KCODE = 8192;
constexpr int NROWS = 16 * 2048;   // 32768

constexpr int BM = 64;    // rows per block
constexpr int BN = 128;   // codes per tile
constexpr int BD = 32;    // depth chunk

// Scratch (no allocations allowed in kernel_launch)
__device__ float g_e2[KCODE];
__device__ float g_x2[NROWS];
__device__ int   g_best[NROWS];

// ---------------------------------------------------------------------------
// Kernel A: squared norms of embedding rows and latent rows (one warp per row)
// ---------------------------------------------------------------------------
__global__ void sumsq_kernel(const float* __restrict__ X, const float* __restrict__ E) {
    int w    = (blockIdx.x * blockDim.x + threadIdx.x) >> 5;
    int lane = threadIdx.x & 31;
    if (w >= KCODE + NROWS) return;
    const float* src = (w < KCODE) ? (E + (size_t)w * DDIM)
                                   : (X + (size_t)(w - KCODE) * DDIM);
    const float4* p = (const float4*)src;
    float s = 0.f;
#pragma unroll
    for (int i = 0; i < 4; i++) {
        float4 v = p[lane + 32 * i];
        s += v.x * v.x + v.y * v.y + v.z * v.z + v.w * v.w;
    }
#pragma unroll
    for (int o = 16; o > 0; o >>= 1) s += __shfl_xor_sync(0xffffffffu, s, o);
    if (lane == 0) {
        if (w < KCODE) g_e2[w] = s;
        else           g_x2[w - KCODE] = s;
    }
}

// ---------------------------------------------------------------------------
// Kernel B: fused fp32 GEMM + argmin.
// Block: 256 threads as 16(ty: row groups) x 16(tx: code groups).
// Each thread: 4 rows x 8 codes micro-tile (codes split tx*4 and 64+tx*4 for
// conflict-free float4 LDS).
// dist replicates the reference expression: (x2 + e2) - 2*dot in fp32,
// with first-occurrence tie-breaking like jnp.argmin.
// ---------------------------------------------------------------------------
__global__ __launch_bounds__(256) void vq_argmin_kernel(
    const float* __restrict__ X, const float* __restrict__ E) {
    __shared__ float Xs[BD][BM];
    __shared__ float Es[BD][BN];
    __shared__ float e2s[BN];
    __shared__ float redD[BM][16];
    __shared__ int   redI[BM][16];

    const int tid  = threadIdx.x;
    const int tx   = tid & 15;
    const int ty   = tid >> 4;
    const int row0 = blockIdx.x * BM;

    float x2[4];
    float bestD[4];
    int   bestI[4];
#pragma unroll
    for (int i = 0; i < 4; i++) {
        bestD[i] = CUDART_INF_F;
        bestI[i] = 0;
        x2[i]    = g_x2[row0 + ty * 4 + i];
    }

    for (int kt = 0; kt < KCODE; kt += BN) {
        float acc[4][8];
#pragma unroll
        for (int i = 0; i < 4; i++)
#pragma unroll
            for (int j = 0; j < 8; j++) acc[i][j] = 0.f;

        if (tid < BN) e2s[tid] = g_e2[kt + tid];   // consumed after syncs below

        for (int d0 = 0; d0 < DDIM; d0 += BD) {
            __syncthreads();
            {   // X tile: 64 rows x 32 depth, transposed into Xs[d][r]
                int r  = tid >> 2;
                int dq = (tid & 3) * 8;
                const float* src = X + (size_t)(row0 + r) * DDIM + d0 + dq;
                float4 v0 = *(const float4*)(src);
                float4 v1 = *(const float4*)(src + 4);
                Xs[dq + 0][r] = v0.x; Xs[dq + 1][r] = v0.y;
                Xs[dq + 2][r] = v0.z; Xs[dq + 3][r] = v0.w;
                Xs[dq + 4][r] = v1.x; Xs[dq + 5][r] = v1.y;
                Xs[dq + 6][r] = v1.z; Xs[dq + 7][r] = v1.w;
            }
            {   // E tile: 128 codes x 32 depth, transposed into Es[d][c]
                int c  = tid >> 1;
                int dq = (tid & 1) * 16;
                const float* src = E + (size_t)(kt + c) * DDIM + d0 + dq;
#pragma unroll
                for (int t = 0; t < 4; t++) {
                    float4 v = *(const float4*)(src + 4 * t);
                    Es[dq + 4 * t + 0][c] = v.x; Es[dq + 4 * t + 1][c] = v.y;
                    Es[dq + 4 * t + 2][c] = v.z; Es[dq + 4 * t + 3][c] = v.w;
                }
            }
            __syncthreads();
#pragma unroll
            for (int d = 0; d < BD; d++) {
                float4 xa = *(const float4*)&Xs[d][ty * 4];
                float4 ea = *(const float4*)&Es[d][tx * 4];
                float4 eb = *(const float4*)&Es[d][64 + tx * 4];
                float xv[4] = {xa.x, xa.y, xa.z, xa.w};
                float ev[8] = {ea.x, ea.y, ea.z, ea.w, eb.x, eb.y, eb.z, eb.w};
#pragma unroll
                for (int i = 0; i < 4; i++)
#pragma unroll
                    for (int j = 0; j < 8; j++) acc[i][j] += xv[i] * ev[j];
            }
        }

        // dist eval for this code tile; strict < + ascending code order within
        // a thread keeps the first-occurrence semantics of jnp.argmin.
#pragma unroll
        for (int i = 0; i < 4; i++) {
#pragma unroll
            for (int j = 0; j < 8; j++) {
                int   cl   = (j < 4) ? (tx * 4 + j) : (64 + tx * 4 + (j - 4));
                float t    = x2[i] + e2s[cl];
                float dist = t - 2.0f * acc[i][j];
                if (dist < bestD[i]) { bestD[i] = dist; bestI[i] = kt + cl; }
            }
        }
        __syncthreads();   // protect e2s before next tile overwrites it
    }

    // cross-thread (tx) reduction per row, tie -> lowest index
#pragma unroll
    for (int i = 0; i < 4; i++) {
        redD[ty * 4 + i][tx] = bestD[i];
        redI[ty * 4 + i][tx] = bestI[i];
    }
    __syncthreads();
    if (tid < BM) {
        float bd = redD[tid][0];
        int   bi = redI[tid][0];
#pragma unroll
        for (int t = 1; t < 16; t++) {
            float d2 = redD[tid][t];
            int   i2 = redI[tid][t];
            if (d2 < bd || (d2 == bd && i2 < bi)) { bd = d2; bi = i2; }
        }
        g_best[row0 + tid] = bi;
    }
}

// ---------------------------------------------------------------------------
// Kernel C: gather selected code vectors into the output
// ---------------------------------------------------------------------------
__global__ void gather_kernel(const float* __restrict__ E, float* __restrict__ out) {
    int r = blockIdx.x;
    int c = g_best[r];
    const float4* src = (const float4*)(E + (size_t)c * DDIM);
    float4*       dst = (float4*)(out + (size_t)r * DDIM);
    dst[threadIdx.x] = src[threadIdx.x];
}

// ---------------------------------------------------------------------------
extern "C" void kernel_launch(void* const* d_in, const int* in_sizes, int n_in,
                              void* d_out, int out_size) {
    const float* X = (const float*)d_in[0];   // latents [32768, 512]
    const float* E = (const float*)d_in[1];   // embedding [8192, 512]
    float* out = (float*)d_out;

    int warps  = KCODE + NROWS;               // one warp per row
    int blocks = (warps * 32 + 255) / 256;
    sumsq_kernel<<<blocks, 256>>>(X, E);
    vq_argmin_kernel<<<NROWS / BM, 256>>>(X, E);
    gather_kernel<<<NROWS, 128>>>(E, out);
}

// round 4
// speedup vs baseline: 1.2918x; 1.2918x over previous
#include <cuda_runtime.h>
#include <math_constants.h>
#include <cstdint>

// Shapes: latents [16,2048,512] -> [32768,512], embedding [8192,512]
constexpr int DDIM  = 512;
constexpr int KCODE = 8192;
constexpr int NROWS = 16 * 2048;

constexpr int TM = 128;          // rows per CTA
constexpr int TN = 128;          // codes per CTA
constexpr int KB = 32;           // k floats per stage
constexpr int NSTAGE = 3;
constexpr int NKS = DDIM / KB;   // 16
constexpr int NRT = NROWS / TM;  // 256
constexpr int NCT = KCODE / TN;  // 64

constexpr uint32_t STAGE_BYTES = TM * KB * 8;              // 32768
constexpr uint32_t B_OFF       = NSTAGE * STAGE_BYTES;     // 98304
constexpr uint32_t SMEM_BYTES  = 2 * NSTAGE * STAGE_BYTES; // 196608

// ---------------- scratch ----------------
__device__ float2 g_Xi[NROWS * DDIM];           // {tf32_hi, tf32_lo}
__device__ float2 g_Ei[KCODE * DDIM];
__device__ float  g_e2[KCODE];
__device__ float  g_x2[NROWS];
__device__ float  g_dot[(size_t)NROWS * KCODE]; // 1 GB dot matrix
__device__ int    g_best[NROWS];

// ---------------- helpers ----------------
__device__ __forceinline__ uint32_t smem_u32(const void* p) {
    uint32_t a;
    asm("{ .reg .u64 t; cvta.to.shared.u64 t, %1; cvt.u32.u64 %0, t; }" : "=r"(a) : "l"(p));
    return a;
}
__device__ __forceinline__ float tf32_rna(float x) {
    uint32_t u;
    asm("cvt.rna.tf32.f32 %0, %1;" : "=r"(u) : "f"(x));
    return __uint_as_float(u);
}
__device__ __forceinline__ int sw_idx(int kc, int row, int k) {
    return (kc * 128 + row) * 8 + (k ^ ((row & 2) << 1));
}
__device__ __forceinline__ void mma8(float* d, const uint32_t* a, const uint32_t* b) {
    asm volatile(
        "mma.sync.aligned.m16n8k8.row.col.f32.tf32.tf32.f32 "
        "{%0,%1,%2,%3}, {%4,%5,%6,%7}, {%8,%9}, {%0,%1,%2,%3};"
        : "+f"(d[0]), "+f"(d[1]), "+f"(d[2]), "+f"(d[3])
        : "r"(a[0]), "r"(a[1]), "r"(a[2]), "r"(a[3]), "r"(b[0]), "r"(b[1]));
}
#define CP_ASYNC16(dst, src) \
    asm volatile("cp.async.cg.shared.global [%0], [%1], 16;" :: "r"(dst), "l"(src) : "memory")
#define CP_COMMIT()  asm volatile("cp.async.commit_group;" ::: "memory")
#define CP_WAIT1()   asm volatile("cp.async.wait_group 1;" ::: "memory")

// ---------------------------------------------------------------------------
// Kernel 1: norms (exact structure of the R1-passing kernel) + tf32 hi/lo split
// ---------------------------------------------------------------------------
__global__ void prep_kernel(const float* __restrict__ X, const float* __restrict__ E) {
    int w    = (blockIdx.x * blockDim.x + threadIdx.x) >> 5;
    int lane = threadIdx.x & 31;
    if (w >= KCODE + NROWS) return;
    bool isE = (w < KCODE);
    int  r   = isE ? w : (w - KCODE);
    const float4* p = (const float4*)(isE ? (E + (size_t)r * DDIM) : (X + (size_t)r * DDIM));

    float s = 0.f;
#pragma unroll
    for (int i = 0; i < 4; i++) {
        float4 v = p[lane + 32 * i];
        s += v.x * v.x + v.y * v.y + v.z * v.z + v.w * v.w;
    }
#pragma unroll
    for (int o = 16; o > 0; o >>= 1) s += __shfl_xor_sync(0xffffffffu, s, o);
    if (lane == 0) {
        if (isE) g_e2[r] = s;
        else     g_x2[r] = s;
    }

    float2* dst = (isE ? g_Ei : g_Xi) + (size_t)r * DDIM;
#pragma unroll
    for (int i = 0; i < 4; i++) {
        float4 v = p[lane + 32 * i];
        float vv[4] = {v.x, v.y, v.z, v.w};
#pragma unroll
        for (int j = 0; j < 4; j++) {
            float h = tf32_rna(vv[j]);
            float l = tf32_rna(vv[j] - h);
            dst[(lane + 32 * i) * 4 + j] = make_float2(h, l);
        }
    }
}

// ---------------------------------------------------------------------------
// Kernel 2: 3xTF32 mma.sync GEMM (128x128 tile, K=512); stores dot matrix.
// ---------------------------------------------------------------------------
__global__ __launch_bounds__(256, 1) void vq_mma_kernel() {
    extern __shared__ char smem[];
    const uint32_t sb = smem_u32(smem);
    const int tid = threadIdx.x;
    const int wid = tid >> 5, lane = tid & 31;
    const int g = lane >> 2, tig = lane & 3;
    const int wm = wid & 3, wn = wid >> 2;          // warp grid 4 x 2
    const int rt = blockIdx.x >> 6;                 // col-tile fastest (L2 reuse)
    const int ct = blockIdx.x & 63;
    const int row0 = rt * TM;
    const int col0 = ct * TN;

    auto stage_cp = [&](int s, int ks) {
#pragma unroll
        for (int i = 0; i < 8; i++) {               // A
            int u = tid + 256 * i, row = u >> 4, t = u & 15;
            int kc = t >> 2, kin = (t & 3) * 2;
            int kp = kin ^ ((row & 2) << 1);
            const float2* src = g_Xi + (size_t)(row0 + row) * DDIM + ks + 2 * t;
            uint32_t dst = sb + (uint32_t)s * STAGE_BYTES +
                           (uint32_t)(((kc * 128 + row) * 8 + kp) * 8);
            CP_ASYNC16(dst, src);
        }
#pragma unroll
        for (int i = 0; i < 8; i++) {               // B
            int u = tid + 256 * i, row = u >> 4, t = u & 15;
            int kc = t >> 2, kin = (t & 3) * 2;
            int kp = kin ^ ((row & 2) << 1);
            const float2* src = g_Ei + (size_t)(col0 + row) * DDIM + ks + 2 * t;
            uint32_t dst = sb + B_OFF + (uint32_t)s * STAGE_BYTES +
                           (uint32_t)(((kc * 128 + row) * 8 + kp) * 8);
            CP_ASYNC16(dst, src);
        }
    };

    float acc[2][8][4];
#pragma unroll
    for (int mt = 0; mt < 2; mt++)
#pragma unroll
        for (int nt = 0; nt < 8; nt++)
#pragma unroll
            for (int q = 0; q < 4; q++) acc[mt][nt][q] = 0.f;

    stage_cp(0, 0);  CP_COMMIT();
    stage_cp(1, KB); CP_COMMIT();

    for (int ks = 0; ks < NKS; ks++) {
        CP_WAIT1();
        __syncthreads();
        if (ks < NKS - 2) stage_cp((ks + 2) % NSTAGE, (ks + 2) * KB);
        CP_COMMIT();

        const int buf = ks % NSTAGE;
        const float2* As = (const float2*)(smem + (size_t)buf * STAGE_BYTES);
        const float2* Bs = (const float2*)(smem + B_OFF + (size_t)buf * STAGE_BYTES);
#pragma unroll
        for (int kc = 0; kc < 4; kc++) {
            uint32_t ah[2][4], al[2][4];
#pragma unroll
            for (int mt = 0; mt < 2; mt++) {
                int r = wm * 32 + mt * 16 + g;
                float2 e0 = As[sw_idx(kc, r,     tig)];
                float2 e1 = As[sw_idx(kc, r + 8, tig)];
                float2 e2v = As[sw_idx(kc, r,     tig + 4)];
                float2 e3 = As[sw_idx(kc, r + 8, tig + 4)];
                ah[mt][0] = __float_as_uint(e0.x); al[mt][0] = __float_as_uint(e0.y);
                ah[mt][1] = __float_as_uint(e1.x); al[mt][1] = __float_as_uint(e1.y);
                ah[mt][2] = __float_as_uint(e2v.x); al[mt][2] = __float_as_uint(e2v.y);
                ah[mt][3] = __float_as_uint(e3.x); al[mt][3] = __float_as_uint(e3.y);
            }
            uint32_t bh[8][2], bl[8][2];
#pragma unroll
            for (int nt = 0; nt < 8; nt++) {
                int n = wn * 64 + nt * 8 + g;
                float2 f0 = Bs[sw_idx(kc, n, tig)];
                float2 f1 = Bs[sw_idx(kc, n, tig + 4)];
                bh[nt][0] = __float_as_uint(f0.x); bl[nt][0] = __float_as_uint(f0.y);
                bh[nt][1] = __float_as_uint(f1.x); bl[nt][1] = __float_as_uint(f1.y);
            }
#pragma unroll
            for (int mt = 0; mt < 2; mt++)
#pragma unroll
                for (int nt = 0; nt < 8; nt++) {
                    mma8(acc[mt][nt], ah[mt], bh[nt]);
                    mma8(acc[mt][nt], ah[mt], bl[nt]);
                    mma8(acc[mt][nt], al[mt], bh[nt]);
                }
        }
    }

    // ---- store dot matrix (float2 per thread-fragment pair) ----
#pragma unroll
    for (int mt = 0; mt < 2; mt++) {
#pragma unroll
        for (int rr = 0; rr < 2; rr++) {
            int row = row0 + wm * 32 + mt * 16 + g + rr * 8;
            float2* drow = (float2*)(g_dot + (size_t)row * KCODE);
#pragma unroll
            for (int nt = 0; nt < 8; nt++) {
                int colpair = (col0 + wn * 64 + nt * 8 + 2 * tig) >> 1;
                drow[colpair] = make_float2(acc[mt][nt][rr * 2], acc[mt][nt][rr * 2 + 1]);
            }
        }
    }
}

// ---------------------------------------------------------------------------
// Kernel 3: per-row argmin with exact-fp32 rescue on near-ties.
// One warp per row. Margin covers split error + dist quantization at 512-scale.
// ---------------------------------------------------------------------------
__global__ __launch_bounds__(256) void argmin_rescue_kernel(
    const float* __restrict__ X, const float* __restrict__ E) {
    int w    = (blockIdx.x * blockDim.x + threadIdx.x) >> 5;
    int lane = threadIdx.x & 31;
    if (w >= NROWS) return;
    const int row = w;
    const float* drow = g_dot + (size_t)row * KCODE;

    // pass 1: approximate score min (score = e2 - 2*dot; x2 shift irrelevant here)
    float m = CUDART_INF_F;
#pragma unroll 4
    for (int k = lane; k < KCODE; k += 32) {
        float sc = __ldg(&g_e2[k]) - 2.0f * __ldg(&drow[k]);
        m = fminf(m, sc);
    }
#pragma unroll
    for (int o = 16; o > 0; o >>= 1) m = fminf(m, __shfl_xor_sync(0xffffffffu, m, o));
    const float T = m + 2.5e-4f;

    // pass 2: exact R1-style dist for every candidate within margin
    const float x2v = g_x2[row];
    const float* xr = X + (size_t)row * DDIM;
    unsigned long long best = ~0ull;
    for (int k = lane; k < KCODE; k += 32) {
        float sc = __ldg(&g_e2[k]) - 2.0f * __ldg(&drow[k]);
        if (sc <= T) {
            // exact sequential fp32 dot, identical source form to the R1 kernel
            const float* er = E + (size_t)k * DDIM;
            float acc = 0.f;
            for (int d = 0; d < DDIM; d++) acc += xr[d] * er[d];
            float t    = x2v + g_e2[k];
            float dist = t - 2.0f * acc;
            unsigned long long p =
                ((unsigned long long)__float_as_uint(dist) << 32) | (unsigned)k;
            best = (p < best) ? p : best;
        }
    }
#pragma unroll
    for (int o = 16; o > 0; o >>= 1) {
        unsigned long long q = __shfl_xor_sync(0xffffffffu, best, o);
        best = (q < best) ? q : best;
    }
    if (lane == 0) g_best[row] = (int)(unsigned)(best & 0xffffffffull);
}

// ---------------------------------------------------------------------------
// Kernel 4: gather + replicate STE rounding: out = x + (e[best] - x)
// ---------------------------------------------------------------------------
__global__ void gather_ste_kernel(const float* __restrict__ X,
                                  const float* __restrict__ E,
                                  float* __restrict__ out) {
    int r = blockIdx.x;
    int c = g_best[r];
    float4 e = ((const float4*)(E + (size_t)c * DDIM))[threadIdx.x];
    float4 x = ((const float4*)(X + (size_t)r * DDIM))[threadIdx.x];
    float4 o;
    o.x = __fadd_rn(x.x, __fsub_rn(e.x, x.x));
    o.y = __fadd_rn(x.y, __fsub_rn(e.y, x.y));
    o.z = __fadd_rn(x.z, __fsub_rn(e.z, x.z));
    o.w = __fadd_rn(x.w, __fsub_rn(e.w, x.w));
    ((float4*)(out + (size_t)r * DDIM))[threadIdx.x] = o;
}

// ---------------------------------------------------------------------------
extern "C" void kernel_launch(void* const* d_in, const int* in_sizes, int n_in,
                              void* d_out, int out_size) {
    const float* X = (const float*)d_in[0];
    const float* E = (const float*)d_in[1];
    float* out = (float*)d_out;

    cudaFuncSetAttribute(vq_mma_kernel, cudaFuncAttributeMaxDynamicSharedMemorySize,
                         SMEM_BYTES);

    int warps = KCODE + NROWS;
    prep_kernel<<<(warps * 32 + 255) / 256, 256>>>(X, E);
    vq_mma_kernel<<<NRT * NCT, 256, SMEM_BYTES>>>();
    argmin_rescue_kernel<<<(NROWS * 32 + 255) / 256, 256>>>(X, E);
    gather_ste_kernel<<<NROWS, 128>>>(X, E, out);
}

// round 6
// speedup vs baseline: 4.8959x; 3.7901x over previous
#include <cuda_runtime.h>
#include <cuda_bf16.h>
#include <cuda_fp16.h>
#include <math_constants.h>
#include <cstdint>

// Shapes: latents [16,2048,512] -> [32768,512], embedding [8192,512]
constexpr int DDIM  = 512;
constexpr int KCODE = 8192;
constexpr int NROWS = 16 * 2048;

constexpr int TM = 128;          // rows per CTA
constexpr int TN = 128;          // codes per CTA
constexpr int KB = 64;           // k elems (bf16) per stage = 128B/row
constexpr int NSTAGE = 3;
constexpr int NKS = DDIM / KB;   // 8
constexpr int NRT = NROWS / TM;  // 256
constexpr int NCT = KCODE / TN;  // 64

constexpr uint32_t STAGE_BYTES = TM * KB * 2;               // 16384
constexpr uint32_t B_OFF       = NSTAGE * STAGE_BYTES;      // 49152
constexpr uint32_t SMEM_BYTES  = 2 * NSTAGE * STAGE_BYTES;  // 98304

// ---------------- scratch ----------------
__device__ __nv_bfloat16 g_Xb[NROWS * DDIM];
__device__ __nv_bfloat16 g_Eb[KCODE * DDIM];
__device__ float  g_e2[KCODE];
__device__ float  g_x2[NROWS];
__device__ __half g_score[(size_t)NROWS * KCODE];   // 512 MB approx scores
__device__ int    g_best[NROWS];

// ---------------- helpers ----------------
__device__ __forceinline__ uint32_t smem_u32(const void* p) {
    uint32_t a;
    asm("{ .reg .u64 t; cvta.to.shared.u64 t, %1; cvt.u32.u64 %0, t; }" : "=r"(a) : "l"(p));
    return a;
}
__device__ __forceinline__ void mma16(float* d, const uint32_t* a, const uint32_t* b) {
    asm volatile(
        "mma.sync.aligned.m16n8k16.row.col.f32.bf16.bf16.f32 "
        "{%0,%1,%2,%3}, {%4,%5,%6,%7}, {%8,%9}, {%0,%1,%2,%3};"
        : "+f"(d[0]), "+f"(d[1]), "+f"(d[2]), "+f"(d[3])
        : "r"(a[0]), "r"(a[1]), "r"(a[2]), "r"(a[3]), "r"(b[0]), "r"(b[1]));
}
#define CP_ASYNC16(dst, src) \
    asm volatile("cp.async.cg.shared.global [%0], [%1], 16;" :: "r"(dst), "l"(src) : "memory")
#define CP_COMMIT()  asm volatile("cp.async.commit_group;" ::: "memory")
#define CP_WAIT1()   asm volatile("cp.async.wait_group 1;" ::: "memory")

// ---------------------------------------------------------------------------
// Kernel 1: norms (exact structure of the R1-passing kernel) + bf16 convert
// ---------------------------------------------------------------------------
__global__ void prep_kernel(const float* __restrict__ X, const float* __restrict__ E) {
    int w    = (blockIdx.x * blockDim.x + threadIdx.x) >> 5;
    int lane = threadIdx.x & 31;
    if (w >= KCODE + NROWS) return;
    bool isE = (w < KCODE);
    int  r   = isE ? w : (w - KCODE);
    const float4* p = (const float4*)(isE ? (E + (size_t)r * DDIM) : (X + (size_t)r * DDIM));

    float s = 0.f;
#pragma unroll
    for (int i = 0; i < 4; i++) {
        float4 v = p[lane + 32 * i];
        s += v.x * v.x + v.y * v.y + v.z * v.z + v.w * v.w;
    }
#pragma unroll
    for (int o = 16; o > 0; o >>= 1) s += __shfl_xor_sync(0xffffffffu, s, o);
    if (lane == 0) {
        if (isE) g_e2[r] = s;
        else     g_x2[r] = s;
    }

    __nv_bfloat162* dst =
        (__nv_bfloat162*)((isE ? g_Eb : g_Xb) + (size_t)r * DDIM);
#pragma unroll
    for (int i = 0; i < 4; i++) {
        float4 v = p[lane + 32 * i];
        dst[(lane + 32 * i) * 2 + 0] = __floats2bfloat162_rn(v.x, v.y);
        dst[(lane + 32 * i) * 2 + 1] = __floats2bfloat162_rn(v.z, v.w);
    }
}

// ---------------------------------------------------------------------------
// Kernel 2: bf16 mma.sync GEMM (128x128 tile, K=512); stores fp16 scores
//           score = e2[col] - 2*dot  (x2 shift irrelevant for ranking)
// SMEM layout per stage: [row][chunk ^ (row&7)] of 16B chunks (8 chunks/row)
// ---------------------------------------------------------------------------
__global__ __launch_bounds__(256, 2) void vq_mma_kernel() {
    extern __shared__ char smem[];
    const uint32_t sb = smem_u32(smem);
    const int tid = threadIdx.x;
    const int wid = tid >> 5, lane = tid & 31;
    const int g = lane >> 2, tig = lane & 3;
    const int wm = wid & 3, wn = wid >> 2;          // warp grid 4 x 2
    const int rt = blockIdx.x >> 6;                 // col-tile fastest (L2 reuse)
    const int ct = blockIdx.x & 63;
    const int row0 = rt * TM;
    const int col0 = ct * TN;

    auto stage_cp = [&](int s, int ks) {
#pragma unroll
        for (int i = 0; i < 4; i++) {               // A: 1024 16B chunks
            int u = tid + 256 * i, row = u >> 3, c = u & 7;
            const void* src = g_Xb + (size_t)(row0 + row) * DDIM + ks + c * 8;
            uint32_t dst = sb + (uint32_t)s * STAGE_BYTES +
                           (uint32_t)(row * 128 + (c ^ (row & 7)) * 16);
            CP_ASYNC16(dst, src);
        }
#pragma unroll
        for (int i = 0; i < 4; i++) {               // B: 1024 16B chunks
            int u = tid + 256 * i, row = u >> 3, c = u & 7;
            const void* src = g_Eb + (size_t)(col0 + row) * DDIM + ks + c * 8;
            uint32_t dst = sb + B_OFF + (uint32_t)s * STAGE_BYTES +
                           (uint32_t)(row * 128 + (c ^ (row & 7)) * 16);
            CP_ASYNC16(dst, src);
        }
    };

    float acc[2][8][4];
#pragma unroll
    for (int mt = 0; mt < 2; mt++)
#pragma unroll
        for (int nt = 0; nt < 8; nt++)
#pragma unroll
            for (int q = 0; q < 4; q++) acc[mt][nt][q] = 0.f;

    stage_cp(0, 0);  CP_COMMIT();
    stage_cp(1, KB); CP_COMMIT();

    for (int ks = 0; ks < NKS; ks++) {
        CP_WAIT1();
        __syncthreads();
        if (ks < NKS - 2) stage_cp((ks + 2) % NSTAGE, (ks + 2) * KB);
        CP_COMMIT();

        const int buf = ks % NSTAGE;
        const char* As = smem + (size_t)buf * STAGE_BYTES;
        const char* Bs = smem + B_OFF + (size_t)buf * STAGE_BYTES;

        // word fetch: (r, s16, h) -> 4B at r*128 + ((2*s16+h)^(r&7))*16 + tig*4
#pragma unroll
        for (int s16 = 0; s16 < 4; s16++) {
            uint32_t a[2][4];
#pragma unroll
            for (int mt = 0; mt < 2; mt++) {
                int r0 = wm * 32 + mt * 16 + g;
                int r1 = r0 + 8;
                a[mt][0] = *(const uint32_t*)(As + r0 * 128 + ((2 * s16 + 0) ^ (r0 & 7)) * 16 + tig * 4);
                a[mt][1] = *(const uint32_t*)(As + r1 * 128 + ((2 * s16 + 0) ^ (r1 & 7)) * 16 + tig * 4);
                a[mt][2] = *(const uint32_t*)(As + r0 * 128 + ((2 * s16 + 1) ^ (r0 & 7)) * 16 + tig * 4);
                a[mt][3] = *(const uint32_t*)(As + r1 * 128 + ((2 * s16 + 1) ^ (r1 & 7)) * 16 + tig * 4);
            }
#pragma unroll
            for (int nt = 0; nt < 8; nt++) {
                int n = wn * 64 + nt * 8 + g;
                uint32_t b[2];
                b[0] = *(const uint32_t*)(Bs + n * 128 + ((2 * s16 + 0) ^ (n & 7)) * 16 + tig * 4);
                b[1] = *(const uint32_t*)(Bs + n * 128 + ((2 * s16 + 1) ^ (n & 7)) * 16 + tig * 4);
                mma16(acc[0][nt], a[0], b);
                mma16(acc[1][nt], a[1], b);
            }
        }
    }

    // ---- epilogue: score = e2 - 2*dot, stored fp16 ----
#pragma unroll
    for (int mt = 0; mt < 2; mt++) {
#pragma unroll
        for (int rr = 0; rr < 2; rr++) {
            int row = row0 + wm * 32 + mt * 16 + g + rr * 8;
            __half* srow = g_score + ((size_t)row << 13);
#pragma unroll
            for (int nt = 0; nt < 8; nt++) {
                int col = col0 + wn * 64 + nt * 8 + 2 * tig;
                float s0 = __ldg(&g_e2[col])     - 2.0f * acc[mt][nt][rr * 2];
                float s1 = __ldg(&g_e2[col + 1]) - 2.0f * acc[mt][nt][rr * 2 + 1];
                *(__half2*)(srow + col) = __floats2half2_rn(s0, s1);
            }
        }
    }
}

// ---------------------------------------------------------------------------
// Kernel 3: per-row argmin with exact-fp32 rescue on near-ties (one warp/row).
// Margin 1.2e-3 covers: bf16 worst-case dot error (<=~2.7e-4, both sides),
// reference dist quantization window (~1.9e-4), half storage (4e-6).
// ---------------------------------------------------------------------------
__global__ __launch_bounds__(256) void argmin_rescue_kernel(
    const float* __restrict__ X, const float* __restrict__ E) {
    int w    = (blockIdx.x * blockDim.x + threadIdx.x) >> 5;
    int lane = threadIdx.x & 31;
    if (w >= NROWS) return;
    const int row = w;
    const uint4* sv = (const uint4*)(g_score + ((size_t)row << 13));

    // pass 1: approximate min
    float m = CUDART_INF_F;
#pragma unroll 4
    for (int it = 0; it < 32; it++) {
        uint4 v = __ldg(&sv[lane + 32 * it]);
        const __half2* h = (const __half2*)&v;
#pragma unroll
        for (int q = 0; q < 4; q++) {
            float2 f = __half22float2(h[q]);
            m = fminf(m, fminf(f.x, f.y));
        }
    }
#pragma unroll
    for (int o = 16; o > 0; o >>= 1) m = fminf(m, __shfl_xor_sync(0xffffffffu, m, o));
    const float T = m + 1.2e-3f;

    // pass 2: exact R1-style dist for every candidate within margin
    const float x2v = g_x2[row];
    const float* xr = X + (size_t)row * DDIM;
    unsigned long long best = ~0ull;
    for (int it = 0; it < 32; it++) {
        uint4 v = __ldg(&sv[lane + 32 * it]);
        const __half2* h = (const __half2*)&v;
#pragma unroll
        for (int q = 0; q < 4; q++) {
            float2 f = __half22float2(h[q]);
            float sc2[2] = {f.x, f.y};
#pragma unroll
            for (int e = 0; e < 2; e++) {
                if (sc2[e] <= T) {
                    int k = (lane + 32 * it) * 8 + q * 2 + e;
                    const float* er = E + (size_t)k * DDIM;
                    float acc = 0.f;
                    for (int d = 0; d < DDIM; d++) acc += xr[d] * er[d];
                    float t    = x2v + g_e2[k];
                    float dist = t - 2.0f * acc;
                    unsigned long long p =
                        ((unsigned long long)__float_as_uint(dist) << 32) | (unsigned)k;
                    best = (p < best) ? p : best;
                }
            }
        }
    }
#pragma unroll
    for (int o = 16; o > 0; o >>= 1) {
        unsigned long long q = __shfl_xor_sync(0xffffffffu, best, o);
        best = (q < best) ? q : best;
    }
    if (lane == 0) g_best[row] = (int)(unsigned)(best & 0xffffffffull);
}

// ---------------------------------------------------------------------------
// Kernel 4: gather + replicate STE rounding: out = x + (e[best] - x)
// ---------------------------------------------------------------------------
__global__ void gather_ste_kernel(const float* __restrict__ X,
                                  const float* __restrict__ E,
                                  float* __restrict__ out) {
    int r = blockIdx.x;
    int c = g_best[r];
    float4 e = ((const float4*)(E + (size_t)c * DDIM))[threadIdx.x];
    float4 x = ((const float4*)(X + (size_t)r * DDIM))[threadIdx.x];
    float4 o;
    o.x = __fadd_rn(x.x, __fsub_rn(e.x, x.x));
    o.y = __fadd_rn(x.y, __fsub_rn(e.y, x.y));
    o.z = __fadd_rn(x.z, __fsub_rn(e.z, x.z));
    o.w = __fadd_rn(x.w, __fsub_rn(e.w, x.w));
    ((float4*)(out + (size_t)r * DDIM))[threadIdx.x] = o;
}

// ---------------------------------------------------------------------------
extern "C" void kernel_launch(void* const* d_in, const int* in_sizes, int n_in,
                              void* d_out, int out_size) {
    const float* X = (const float*)d_in[0];
    const float* E = (const float*)d_in[1];
    float* out = (float*)d_out;

    cudaFuncSetAttribute(vq_mma_kernel, cudaFuncAttributeMaxDynamicSharedMemorySize,
                         SMEM_BYTES);

    int warps = KCODE + NROWS;
    prep_kernel<<<(warps * 32 + 255) / 256, 256>>>(X, E);
    vq_mma_kernel<<<NRT * NCT, 256, SMEM_BYTES>>>();
    argmin_rescue_kernel<<<NROWS / 8, 256>>>(X, E);
    gather_ste_kernel<<<NROWS, 128>>>(X, E, out);
}

// round 7
// speedup vs baseline: 5.2152x; 1.0652x over previous
#include <cuda_runtime.h>
#include <cuda_bf16.h>
#include <cuda_fp16.h>
#include <math_constants.h>
#include <cstdint>

// Shapes: latents [16,2048,512] -> [32768,512], embedding [8192,512]
constexpr int DDIM  = 512;
constexpr int KCODE = 8192;
constexpr int NROWS = 16 * 2048;

constexpr int TM = 128;
constexpr int TN = 128;
constexpr int KB = 64;           // bf16 elems per stage row = 128B
constexpr int NSTAGE = 3;
constexpr int NKS = DDIM / KB;   // 8
constexpr int NRT = NROWS / TM;  // 256
constexpr int NCT = KCODE / TN;  // 64

constexpr uint32_t STAGE_BYTES = TM * KB * 2;               // 16384
constexpr uint32_t B_OFF       = NSTAGE * STAGE_BYTES;      // 49152
constexpr uint32_t SMEM_BYTES  = 2 * NSTAGE * STAGE_BYTES;  // 98304

// ---------------- scratch ----------------
__device__ __nv_bfloat16 g_Xb[NROWS * DDIM];
__device__ __nv_bfloat16 g_Eb[KCODE * DDIM];
__device__ float    g_e2[KCODE];
__device__ float    g_x2[NROWS];
__device__ __half   g_score[(size_t)NROWS * KCODE];   // 512 MB approx scores
__device__ unsigned g_rowmin[NROWS];                  // float-ordered keys

// ---------------- helpers ----------------
__device__ __forceinline__ uint32_t smem_u32(const void* p) {
    uint32_t a;
    asm("{ .reg .u64 t; cvta.to.shared.u64 t, %1; cvt.u32.u64 %0, t; }" : "=r"(a) : "l"(p));
    return a;
}
__device__ __forceinline__ unsigned fkey(float f) {          // order-preserving
    unsigned b = __float_as_uint(f);
    return b ^ (unsigned)(((int)b >> 31) | 0x80000000);
}
__device__ __forceinline__ float funkey(unsigned k) {
    unsigned b = k ^ (unsigned)((~(int)k >> 31) | 0x80000000);
    return __uint_as_float(b);
}
__device__ __forceinline__ void mma16(float* d, const uint32_t* a, const uint32_t* b) {
    asm volatile(
        "mma.sync.aligned.m16n8k16.row.col.f32.bf16.bf16.f32 "
        "{%0,%1,%2,%3}, {%4,%5,%6,%7}, {%8,%9}, {%0,%1,%2,%3};"
        : "+f"(d[0]), "+f"(d[1]), "+f"(d[2]), "+f"(d[3])
        : "r"(a[0]), "r"(a[1]), "r"(a[2]), "r"(a[3]), "r"(b[0]), "r"(b[1]));
}
#define LDSM_X4(r0, r1, r2, r3, addr)                                            \
    asm volatile("ldmatrix.sync.aligned.m8n8.x4.shared.b16 {%0,%1,%2,%3}, [%4];" \
        : "=r"(r0), "=r"(r1), "=r"(r2), "=r"(r3) : "r"(addr))
#define CP_ASYNC16(dst, src) \
    asm volatile("cp.async.cg.shared.global [%0], [%1], 16;" :: "r"(dst), "l"(src) : "memory")
#define CP_COMMIT()  asm volatile("cp.async.commit_group;" ::: "memory")
#define CP_WAIT1()   asm volatile("cp.async.wait_group 1;" ::: "memory")

// ---------------------------------------------------------------------------
// Kernel 1: norms (R1-proven structure) + bf16 convert + rowmin init
// ---------------------------------------------------------------------------
__global__ void prep_kernel(const float* __restrict__ X, const float* __restrict__ E) {
    int w    = (blockIdx.x * blockDim.x + threadIdx.x) >> 5;
    int lane = threadIdx.x & 31;
    if (w >= KCODE + NROWS) return;
    bool isE = (w < KCODE);
    int  r   = isE ? w : (w - KCODE);
    const float4* p = (const float4*)(isE ? (E + (size_t)r * DDIM) : (X + (size_t)r * DDIM));

    float s = 0.f;
#pragma unroll
    for (int i = 0; i < 4; i++) {
        float4 v = p[lane + 32 * i];
        s += v.x * v.x + v.y * v.y + v.z * v.z + v.w * v.w;
    }
#pragma unroll
    for (int o = 16; o > 0; o >>= 1) s += __shfl_xor_sync(0xffffffffu, s, o);
    if (lane == 0) {
        if (isE) g_e2[r] = s;
        else { g_x2[r] = s; g_rowmin[r] = 0xFFFFFFFFu; }
    }

    __nv_bfloat162* dst = (__nv_bfloat162*)((isE ? g_Eb : g_Xb) + (size_t)r * DDIM);
#pragma unroll
    for (int i = 0; i < 4; i++) {
        float4 v = p[lane + 32 * i];
        dst[(lane + 32 * i) * 2 + 0] = __floats2bfloat162_rn(v.x, v.y);
        dst[(lane + 32 * i) * 2 + 1] = __floats2bfloat162_rn(v.z, v.w);
    }
}

// ---------------------------------------------------------------------------
// Kernel 2: bf16 GEMM (128x128 tile, K=512) via ldmatrix + mma.sync.
// Stores fp16 scores AND per-row approximate min (atomicMin on ordered keys).
// ---------------------------------------------------------------------------
__global__ __launch_bounds__(256, 2) void vq_mma_kernel() {
    extern __shared__ char smem[];
    const uint32_t sb = smem_u32(smem);
    const int tid = threadIdx.x;
    const int wid = tid >> 5, lane = tid & 31;
    const int g = lane >> 2, tig = lane & 3;
    const int wm = wid & 3, wn = wid >> 2;          // warp grid 4 x 2
    const int rt = blockIdx.x >> 6;                 // col-tile fastest (L2 reuse)
    const int ct = blockIdx.x & 63;
    const int row0 = rt * TM;
    const int col0 = ct * TN;

    auto stage_cp = [&](int s, int ks) {
#pragma unroll
        for (int i = 0; i < 4; i++) {               // A: 1024 16B chunks
            int u = tid + 256 * i, row = u >> 3, c = u & 7;
            const void* src = g_Xb + (size_t)(row0 + row) * DDIM + ks + c * 8;
            uint32_t dst = sb + (uint32_t)s * STAGE_BYTES +
                           (uint32_t)(row * 128 + (c ^ (row & 7)) * 16);
            CP_ASYNC16(dst, src);
        }
#pragma unroll
        for (int i = 0; i < 4; i++) {               // B: 1024 16B chunks
            int u = tid + 256 * i, row = u >> 3, c = u & 7;
            const void* src = g_Eb + (size_t)(col0 + row) * DDIM + ks + c * 8;
            uint32_t dst = sb + B_OFF + (uint32_t)s * STAGE_BYTES +
                           (uint32_t)(row * 128 + (c ^ (row & 7)) * 16);
            CP_ASYNC16(dst, src);
        }
    };

    // ldmatrix per-lane source rows (sel = which 8x8 matrix this lane feeds)
    const int lrow = lane & 7, sel = lane >> 3;
    // A(mt): rows wm*32+mt*16 + lrow + (sel&1)*8, chunk parity sel>>1
    int arow[2], acb = sel >> 1;
#pragma unroll
    for (int mt = 0; mt < 2; mt++) arow[mt] = wm * 32 + mt * 16 + lrow + (sel & 1) * 8;
    // B(ntp): rows wn*64 + ntp*16 + (sel>>1)*8 + lrow, chunk parity sel&1
    int brow[4], bcb = sel & 1;
#pragma unroll
    for (int ntp = 0; ntp < 4; ntp++) brow[ntp] = wn * 64 + ntp * 16 + (sel >> 1) * 8 + lrow;

    float acc[2][8][4];
#pragma unroll
    for (int mt = 0; mt < 2; mt++)
#pragma unroll
        for (int nt = 0; nt < 8; nt++)
#pragma unroll
            for (int q = 0; q < 4; q++) acc[mt][nt][q] = 0.f;

    stage_cp(0, 0);  CP_COMMIT();
    stage_cp(1, KB); CP_COMMIT();

    for (int ks = 0; ks < NKS; ks++) {
        CP_WAIT1();
        __syncthreads();
        if (ks < NKS - 2) stage_cp((ks + 2) % NSTAGE, (ks + 2) * KB);
        CP_COMMIT();

        const int buf = ks % NSTAGE;
        const uint32_t As = sb + (uint32_t)buf * STAGE_BYTES;
        const uint32_t Bs = sb + B_OFF + (uint32_t)buf * STAGE_BYTES;

#pragma unroll
        for (int s16 = 0; s16 < 4; s16++) {
            uint32_t a[2][4];
#pragma unroll
            for (int mt = 0; mt < 2; mt++) {
                int c = 2 * s16 + acb;
                uint32_t ad = As + arow[mt] * 128 + ((c ^ (arow[mt] & 7)) * 16);
                LDSM_X4(a[mt][0], a[mt][1], a[mt][2], a[mt][3], ad);
            }
            uint32_t b[8][2];
#pragma unroll
            for (int ntp = 0; ntp < 4; ntp++) {
                int c = 2 * s16 + bcb;
                uint32_t bd = Bs + brow[ntp] * 128 + ((c ^ (brow[ntp] & 7)) * 16);
                LDSM_X4(b[2 * ntp][0], b[2 * ntp][1], b[2 * ntp + 1][0], b[2 * ntp + 1][1], bd);
            }
#pragma unroll
            for (int nt = 0; nt < 8; nt++) {
                mma16(acc[0][nt], a[0], b[nt]);
                mma16(acc[1][nt], a[1], b[nt]);
            }
        }
    }

    // ---- epilogue: score = e2 - 2*dot -> fp16 store + per-row atomic min ----
#pragma unroll
    for (int mt = 0; mt < 2; mt++) {
#pragma unroll
        for (int rr = 0; rr < 2; rr++) {
            int row = row0 + wm * 32 + mt * 16 + g + rr * 8;
            __half* srow = g_score + ((size_t)row << 13);
            float rmin = CUDART_INF_F;
#pragma unroll
            for (int nt = 0; nt < 8; nt++) {
                int col = col0 + wn * 64 + nt * 8 + 2 * tig;
                float s0 = __ldg(&g_e2[col])     - 2.0f * acc[mt][nt][rr * 2];
                float s1 = __ldg(&g_e2[col + 1]) - 2.0f * acc[mt][nt][rr * 2 + 1];
                rmin = fminf(rmin, fminf(s0, s1));
                *(__half2*)(srow + col) = __floats2half2_rn(s0, s1);
            }
            rmin = fminf(rmin, __shfl_xor_sync(0xffffffffu, rmin, 1));
            rmin = fminf(rmin, __shfl_xor_sync(0xffffffffu, rmin, 2));
            if (tig == 0) atomicMin(&g_rowmin[row], fkey(rmin));
        }
    }
}

// ---------------------------------------------------------------------------
// Kernel 3: single-pass rescue + fused gather/STE. One warp per row.
// Margin 1.2e-3 >= bf16 worst case (2.7e-4) + ref tie window (1.9e-4)
//                + half store ulp (1.5e-5), with >2x slack.
// ---------------------------------------------------------------------------
__global__ __launch_bounds__(256) void rescue_gather_kernel(
    const float* __restrict__ X, const float* __restrict__ E,
    float* __restrict__ out) {
    int w    = (blockIdx.x * blockDim.x + threadIdx.x) >> 5;
    int lane = threadIdx.x & 31;
    if (w >= NROWS) return;
    const int row = w;
    const uint4* sv = (const uint4*)(g_score + ((size_t)row << 13));
    const float Tf = funkey(g_rowmin[row]) + 1.2e-3f;

    const float x2v = g_x2[row];
    const float* xr = X + (size_t)row * DDIM;
    unsigned long long best = ~0ull;

    for (int it = 0; it < 32; it++) {
        uint4 v = __ldg(&sv[lane + 32 * it]);
        __half2 h0 = *(__half2*)&v.x, h1 = *(__half2*)&v.y;
        __half2 h2 = *(__half2*)&v.z, h3 = *(__half2*)&v.w;
        __half2 mn2 = __hmin2(__hmin2(h0, h1), __hmin2(h2, h3));
        float mn = fminf(__low2float(mn2), __high2float(mn2));
        if (mn <= Tf) {                               // rare: ~1 hit / row
            const __half2 hh[4] = {h0, h1, h2, h3};
#pragma unroll
            for (int q = 0; q < 4; q++) {
                float2 f = __half22float2(hh[q]);
                float sc2[2] = {f.x, f.y};
#pragma unroll
                for (int e = 0; e < 2; e++) {
                    if (sc2[e] <= Tf) {
                        int k = (lane + 32 * it) * 8 + q * 2 + e;
                        const float* er = E + (size_t)k * DDIM;
                        float acc = 0.f;
                        for (int d = 0; d < DDIM; d++) acc += xr[d] * er[d];
                        float t    = x2v + g_e2[k];
                        float dist = t - 2.0f * acc;   // exact R1-form dist
                        unsigned long long p =
                            ((unsigned long long)__float_as_uint(dist) << 32) | (unsigned)k;
                        best = (p < best) ? p : best;
                    }
                }
            }
        }
    }
#pragma unroll
    for (int o = 16; o > 0; o >>= 1) {
        unsigned long long q = __shfl_xor_sync(0xffffffffu, best, o);
        best = (q < best) ? q : best;
    }
    const int c = (int)(unsigned)(best & 0xffffffffull);

    // fused gather + STE rounding: out = x + (e - x)
    const float4* ep = (const float4*)(E + (size_t)c * DDIM);
    const float4* xp = (const float4*)xr;
    float4* op = (float4*)(out + (size_t)row * DDIM);
#pragma unroll
    for (int i = 0; i < 4; i++) {
        float4 e = ep[lane + 32 * i];
        float4 x = xp[lane + 32 * i];
        float4 o;
        o.x = __fadd_rn(x.x, __fsub_rn(e.x, x.x));
        o.y = __fadd_rn(x.y, __fsub_rn(e.y, x.y));
        o.z = __fadd_rn(x.z, __fsub_rn(e.z, x.z));
        o.w = __fadd_rn(x.w, __fsub_rn(e.w, x.w));
        op[lane + 32 * i] = o;
    }
}

// ---------------------------------------------------------------------------
extern "C" void kernel_launch(void* const* d_in, const int* in_sizes, int n_in,
                              void* d_out, int out_size) {
    const float* X = (const float*)d_in[0];
    const float* E = (const float*)d_in[1];
    float* out = (float*)d_out;

    cudaFuncSetAttribute(vq_mma_kernel, cudaFuncAttributeMaxDynamicSharedMemorySize,
                         SMEM_BYTES);

    int warps = KCODE + NROWS;
    prep_kernel<<<(warps * 32 + 255) / 256, 256>>>(X, E);
    vq_mma_kernel<<<NRT * NCT, 256, SMEM_BYTES>>>();
    rescue_gather_kernel<<<NROWS / 8, 256>>>(X, E, out);
}